// round 15
// baseline (speedup 1.0000x reference)
#include <cuda_runtime.h>
#include <cuda_bf16.h>
#include <stdint.h>

#define BB 4
#define CC 64
#define HH 128
#define WW 128
#define NTOT 22246u

// ---------------- scratch (__device__ globals: allocation-free) ----------------
__device__ float d_buf_o[BB*CC*HH*WW];
__device__ float d_stats[2*BB*CC];
__device__ __align__(128) __nv_bfloat16 d_wb[998ull*8192];
// atiles: 0:x 1:bo 2:m1/mid 3:m3 4:m5
__device__ __align__(128) __nv_bfloat16 d_at[5][(size_t)BB*HH*16384];

__device__ volatile unsigned g_phase;
__device__ unsigned g_cnt;
__device__ unsigned d_claim;
__device__ unsigned d_segdone[46];
__device__ unsigned char d_flag[39*512];

__constant__ int c_mfej[9] = {-1,0,-1,1,-1,2,-1,3,4};

struct MegaArgs {
    const float *x,*cf1,*cf2,*map_,*resw,*resb,*mw1,*mb1,*mw3,*mb3,*mw5,*mb5,
                *caw1,*caw2,*fcw,*fcb;
    float* out;
};
struct Epi {
    const float *bias,*res,*cg,*map,*xres;
    float* out;
    __nv_bfloat16* atout;
    int act;
};

// smem layout (single A buffer, double B, cg slot)
#define WPU 132
#define ALO (WPU*128)
#define ASZ (WPU*256)
#define BOFF ASZ
#define CGOFF (BOFF+32768)
#define SMEMSZ (CGOFF+1024+128)

// ---------------- helpers ----------------
__device__ __forceinline__ uint32_t smem_u32(const void* p){
    uint32_t a;
    asm("{ .reg .u64 t; cvta.to.shared.u64 t, %1; cvt.u32.u64 %0, t; }":"=r"(a):"l"(p));
    return a;
}
#define LDSM4(r, a) \
    asm volatile("ldmatrix.sync.aligned.m8n8.x4.shared.b16 {%0,%1,%2,%3}, [%4];" \
        : "=r"((r)[0]),"=r"((r)[1]),"=r"((r)[2]),"=r"((r)[3]) : "r"(a))

__device__ __forceinline__ void mma16816(float* c, const uint32_t* a,
                                         uint32_t b0, uint32_t b1){
    asm volatile("mma.sync.aligned.m16n8k16.row.col.f32.bf16.bf16.f32 "
        "{%0,%1,%2,%3}, {%4,%5,%6,%7}, {%8,%9}, {%0,%1,%2,%3};"
        : "+f"(c[0]),"+f"(c[1]),"+f"(c[2]),"+f"(c[3])
        : "r"(a[0]),"r"(a[1]),"r"(a[2]),"r"(a[3]), "r"(b0),"r"(b1));
}
__device__ __forceinline__ void split_pack(float v0, float v1, uint32_t& hp, uint32_t& lp){
    const __nv_bfloat16 h0=__float2bfloat16(v0), h1=__float2bfloat16(v1);
    const __nv_bfloat16 l0=__float2bfloat16(v0-__bfloat162float(h0));
    const __nv_bfloat16 l1=__float2bfloat16(v1-__bfloat162float(h1));
    hp = (uint32_t)__bfloat16_as_ushort(h0) | ((uint32_t)__bfloat16_as_ushort(h1)<<16);
    lp = (uint32_t)__bfloat16_as_ushort(l0) | ((uint32_t)__bfloat16_as_ushort(l1)<<16);
}

// ---------------- grid barrier (one use: after zeroing sync state) ----------------
__device__ __forceinline__ void gridbar(unsigned& lph, int ncta){
    __syncthreads();
    if (threadIdx.x==0){
        const unsigned target = ++lph;
        __threadfence();
        if (atomicAdd(&g_cnt,1u) == (unsigned)ncta-1u){
            atomicExch(&g_cnt, 0u);
            __threadfence();
            g_phase = target;
        } else {
            while (g_phase < target) __nanosleep(64);
        }
        __threadfence();
    }
    __syncthreads();
}

// ---------------- dep waits (tid0 only) ----------------
__device__ __forceinline__ void wait_rows(int f, int b, int lo, int hi){
    volatile unsigned char* fl = d_flag + f*512 + b*128;
    for (int r=lo; r<=hi; r++) while (fl[r]==0) __nanosleep(64);
}
__device__ __forceinline__ void wait_cnt(int s, unsigned n){
    volatile unsigned* p = (volatile unsigned*)&d_segdone[s];
    while (*p < n) __nanosleep(64);
}

// ---------------- weight prep ----------------
__device__ void prep_one(int tile, const MegaArgs& A, float SCALE){
    const float* src; const float* cp = nullptr; float scale = 1.f; int k2, tap;
    if (tile < 360){
        const int conv = tile/36, rem = tile%36, b = rem/9;
        tap = rem%9; k2 = 9; scale = SCALE;
        src = A.resw + (size_t)conv*CC*CC*9;
        cp  = A.cf1 + (size_t)(conv*4 + b)*CC;
    } else if (tile < 648){
        const int t = tile-360, conv = t/36, rem = t%36, b = rem/9;
        tap = rem%9; k2 = 9; scale = SCALE;
        src = A.resw + (size_t)(10+conv)*CC*CC*9;
        cp  = A.cf2 + (size_t)(conv*4 + b)*CC;
    } else if (tile < 658){
        const int c = tile-648;
        tap = 0; k2 = 1;
        src = A.mw1 + (size_t)c*CC*CC;
    } else if (tile < 748){
        const int t = tile-658, conv = t/9;
        tap = t%9; k2 = 9;
        src = A.mw3 + (size_t)conv*CC*CC*9;
    } else {
        const int t = tile-748, conv = t/25;
        tap = t%25; k2 = 25;
        src = A.mw5 + (size_t)conv*CC*CC*25;
    }
    __nv_bfloat16* dst = d_wb + (size_t)tile*8192;
    for (int e=threadIdx.x; e<4096; e+=256){
        const int oc=e>>6, ic=e&63;
        float v = src[(size_t)(oc*CC+ic)*k2 + tap]*scale;
        if (cp) v *= cp[ic];
        const __nv_bfloat16 hb=__float2bfloat16(v);
        const __nv_bfloat16 lb=__float2bfloat16(v-__bfloat162float(hb));
        const uint32_t off=(uint32_t)oc*128+(uint32_t)ic*2;
        const uint32_t sw=off^((off>>3)&0x70);
        dst[sw>>1]=hb;
        dst[4096+(sw>>1)]=lb;
    }
}

// ---------------- ingest one (b,h) row of x ----------------
__device__ void ingest_one(int h, int b, const float* x, char* sm){
    float* raw = (float*)sm;
    char*  at  = sm + BOFF;
    const int tid=threadIdx.x;
    __syncthreads();
    for (int i=tid;i<CC*WW;i+=256){
        const int ic=i>>7, w=i&127;
        raw[i] = x[(((size_t)b*CC+ic)*HH+h)*WW + w];
    }
    __syncthreads();
    const int w=tid&127, half=tid>>7;
    #pragma unroll
    for (int k=0;k<16;k++){
        const int ic=half*32+2*k;
        uint32_t hp, lp;
        split_pack(raw[ic*WW+w], raw[(ic+1)*WW+w], hp, lp);
        const uint32_t ro = (uint32_t)w*128 + ((uint32_t)((ic>>3)^(w&7))<<4) + (uint32_t)(ic&7)*2;
        *(uint32_t*)(at + ro) = hp;
        *(uint32_t*)(at + 16384 + ro) = lp;
    }
    __syncthreads();
    uint4* dst=(uint4*)(d_at[0] + (size_t)(b*HH+h)*16384);
    const uint4* src=(const uint4*)at;
    #pragma unroll
    for (int j=0;j<8;j++) dst[tid+j*256]=src[tid+j*256];
}

// ---------------- conv machinery ----------------
__device__ __forceinline__ void zero_pads1(char* sm){
    const int tid=threadIdx.x;
    if (tid<64){
        const int plane=tid>>5, r=(tid>>3)&3, c=tid&7;
        const int row=(r<2)? r : (128+r);
        ((uint4*)(sm + plane*ALO + row*128))[c]=make_uint4(0,0,0,0);
    }
}
// A (atile) loads: .cg — atiles are rewritten cross-SM; L1 must be bypassed
__device__ __forceinline__ void issueA1(uint32_t sb, const char* abase, int arow){
    const int tid=threadIdx.x;
    const int sz=(arow>=0 && arow<HH)?16:0;
    const int rc=arow<0?0:(arow>127?127:arow);
    const char* src=abase+(size_t)rc*32768;
    const uint32_t d0=sb + 2*128;
    #pragma unroll
    for (int j=0;j<4;j++){
        const int c=tid+j*256;
        asm volatile("cp.async.cg.shared.global [%0], [%1], 16, %2;"
            :: "r"(d0+c*16), "l"(src+c*16), "r"(sz) : "memory");
        asm volatile("cp.async.cg.shared.global [%0], [%1], 16, %2;"
            :: "r"(d0+ALO+c*16), "l"(src+16384+c*16), "r"(sz) : "memory");
    }
}
// B (weights) loads: .ca — d_wb is write-once-before-any-read per launch (gated by
// wait_cnt(39,998)), replay-invariant, and L1 is flushed per launch: L1-cache safe.
__device__ __forceinline__ void issueB(uint32_t sb, const __nv_bfloat16* bptr, int buf){
    const int tid=threadIdx.x;
    const char* src=(const char*)bptr;
    const uint32_t d0=sb+BOFF+(uint32_t)buf*16384;
    #pragma unroll
    for (int j=0;j<4;j++){
        const int c=tid+j*256;
        asm volatile("cp.async.ca.shared.global [%0], [%1], 16;"
            :: "r"(d0+c*16), "l"(src+c*16) : "memory");
    }
}

__device__ __forceinline__ void do_tap2(float acc[2][4][4], uint32_t aB, uint32_t bB,
                                        int s, int m0, int n0, int l){
    #pragma unroll
    for (int ks=0;ks<4;ks++){
        const int ch = ks*2 + (l>>4);
        uint32_t ah[2][4], al[2][4], bh[2][4], bl[2][4];
        #pragma unroll
        for (int mt=0;mt<2;mt++){
            const int row = m0+mt*16+s+(l&15);
            const uint32_t ad = aB + (uint32_t)row*128 + ((uint32_t)(ch ^ ((row-2)&7))<<4);
            LDSM4(ah[mt], ad);
            LDSM4(al[mt], ad + ALO);
        }
        #pragma unroll
        for (int np=0;np<2;np++){
            const int row = n0+np*16+(l&15);
            const uint32_t bd = bB + (uint32_t)row*128 + ((uint32_t)(ch ^ (row&7))<<4);
            LDSM4(bh[np], bd);
            LDSM4(bl[np], bd + 8192);
        }
        #pragma unroll
        for (int mt=0;mt<2;mt++)
            #pragma unroll
            for (int np=0;np<2;np++)
                #pragma unroll
                for (int q=0;q<2;q++)
                    mma16816(acc[mt][np*2+q], ah[mt], bh[np][q], bh[np][2+q]);
        #pragma unroll
        for (int mt=0;mt<2;mt++)
            #pragma unroll
            for (int np=0;np<2;np++)
                #pragma unroll
                for (int q=0;q<2;q++)
                    mma16816(acc[mt][np*2+q], al[mt], bh[np][q], bh[np][2+q]);
        #pragma unroll
        for (int mt=0;mt<2;mt++)
            #pragma unroll
            for (int np=0;np<2;np++)
                #pragma unroll
                for (int q=0;q<2;q++)
                    mma16816(acc[mt][np*2+q], ah[mt], bl[np][q], bl[np][2+q]);
    }
}

__device__ void epilogue(float acc[2][4][4], const Epi& e,
                         const float* bias3, const float* bias5,
                         char* sm, int m0, int n0, int l, int h, int b){
    const int tid=threadIdx.x;
    __syncthreads();
    float* os=(float*)sm;
    #pragma unroll
    for (int mt=0;mt<2;mt++)
        #pragma unroll
        for (int nt=0;nt<4;nt++)
            #pragma unroll
            for (int q=0;q<4;q++){
                const int row=m0+mt*16+(l>>2)+((q>>1)<<3);
                const int col=n0+nt*8+((l&3)<<1)+(q&1);
                os[row*65+col]=acc[mt][nt][q];
            }
    __syncthreads();

    const int w=tid&127, oc0=(tid>>7)*32;
    const size_t pix=(size_t)h*WW+w;
    const float mv = e.map? e.map[(size_t)b*HH*WW+pix] : 0.f;
    char* smA2 = sm + BOFF;
    #pragma unroll 4
    for (int k=0;k<32;k+=2){
        float vv[2];
        #pragma unroll
        for (int s2=0;s2<2;s2++){
            const int oc=oc0+k+s2;
            const size_t idx=((size_t)(b*CC+oc))*HH*WW+pix;
            float v=os[w*65+oc];
            if (e.bias) v+=e.bias[oc];
            if (bias3)  v+=bias3[oc];
            if (bias5)  v+=bias5[oc];
            if (e.act==1)      v=fmaxf(v,0.f);
            else if (e.act==2) v=(v>0.f)?v:0.01f*v;
            if (e.res) v+=__ldcg(e.res+idx);
            if (e.cg)  v*=e.cg[b*CC+oc];
            if (e.map) v=v*mv+e.xres[idx];
            if (e.out) e.out[idx]=v;
            vv[s2]=v;
        }
        if (e.atout){
            const int oc=oc0+k;
            uint32_t hp, lp;
            split_pack(vv[0], vv[1], hp, lp);
            const uint32_t ro = (uint32_t)w*128 + ((uint32_t)((oc>>3)^(w&7))<<4)
                              + (uint32_t)(oc&7)*2;
            *(uint32_t*)(smA2 + ro) = hp;
            *(uint32_t*)(smA2 + 16384 + ro) = lp;
        }
    }
    if (e.atout){
        __syncthreads();
        uint4* dst=(uint4*)(e.atout + (size_t)(b*HH+h)*16384);
        const uint4* src=(const uint4*)smA2;
        #pragma unroll
        for (int j=0;j<8;j++) dst[tid+j*256]=src[tid+j*256];
    }
}

template<int KD>
__device__ void conv_one(int h, int b, const __nv_bfloat16* ain,
                         const __nv_bfloat16* wt, int bstride,
                         const Epi& e, char* sm, uint32_t sb){
    constexpr int PAD=KD/2, TAPS=KD*KD;
    const int tid=threadIdx.x, l=tid&31, wid=tid>>5;
    const int m0=(wid&3)*32, n0=(wid>>2)*32;

    __syncthreads();
    zero_pads1(sm);
    const char* abase=(const char*)ain + (size_t)b*HH*32768;

    float acc[2][4][4];
    #pragma unroll
    for (int mt=0;mt<2;mt++)
        #pragma unroll
        for (int nt=0;nt<4;nt++)
            #pragma unroll
            for (int q=0;q<4;q++) acc[mt][nt][q]=0.f;

    issueA1(sb, abase, h-PAD);
    issueB(sb, wt + (size_t)b*bstride*8192, 0);
    asm volatile("cp.async.commit_group;" ::: "memory");

    int kh=0, kw=0;
    for (int t=0;t<TAPS;t++){
        asm volatile("cp.async.wait_group 0;" ::: "memory");
        __syncthreads();
        if (t+1<TAPS){
            issueB(sb, wt + ((size_t)b*bstride + t+1)*8192, (t+1)&1);
            asm volatile("cp.async.commit_group;" ::: "memory");
        }
        do_tap2(acc, sb, sb+BOFF+(uint32_t)(t&1)*16384, 2+kw-PAD, m0, n0, l);
        kw++; if (kw==KD){kw=0; kh++;}
        if (t+1<TAPS && kw==0){
            __syncthreads();
            issueA1(sb, abase, h+kh-PAD);
            asm volatile("cp.async.commit_group;" ::: "memory");
        }
    }
    epilogue(acc, e, nullptr, nullptr, sm, m0, n0, l, h, b);
}

__device__ void mfeb_one(int h, int b,
                         const __nv_bfloat16* a1, const __nv_bfloat16* a3, const __nv_bfloat16* a5,
                         const __nv_bfloat16* w1, const __nv_bfloat16* w3, const __nv_bfloat16* w5,
                         const float* bias3, const float* bias5, const Epi& e,
                         char* sm, uint32_t sb){
    const int tid=threadIdx.x, l=tid&31, wid=tid>>5;
    const int m0=(wid&3)*32, n0=(wid>>2)*32;

    __syncthreads();
    zero_pads1(sm);
    const char* ab3=(const char*)a3 + (size_t)b*HH*32768;
    const char* ab5=(const char*)a5 + (size_t)b*HH*32768;

    float acc[2][4][4];
    #pragma unroll
    for (int mt=0;mt<2;mt++)
        #pragma unroll
        for (int nt=0;nt<4;nt++)
            #pragma unroll
            for (int q=0;q<4;q++) acc[mt][nt][q]=0.f;

    issueA1(sb, (const char*)a1 + (size_t)b*HH*32768, h);
    issueB(sb, w1, 0);
    asm volatile("cp.async.commit_group;" ::: "memory");

    for (int t=0;t<35;t++){
        asm volatile("cp.async.wait_group 0;" ::: "memory");
        __syncthreads();
        if (t<34){
            const int tn=t+1;
            const __nv_bfloat16* bp = (tn<10)? w3 + (size_t)(tn-1)*8192
                                             : w5 + (size_t)(tn-10)*8192;
            issueB(sb, bp, tn&1);
            asm volatile("cp.async.commit_group;" ::: "memory");
        }
        const int s = (t==0)? 2 : (t<10)? 1+(t-1)%3 : (t-10)%5;
        do_tap2(acc, sb, sb+BOFF+(uint32_t)(t&1)*16384, s, m0, n0, l);
        if (t<34){
            const int tn=t+1;
            bool rel; const char* asrc; int arow;
            if (tn<10){ const int u=tn-1; rel=(u%3==0); asrc=ab3; arow=h+u/3-1; }
            else      { const int u=tn-10; rel=(u%5==0); asrc=ab5; arow=h+u/5-2; }
            if (rel){
                __syncthreads();
                issueA1(sb, asrc, arow);
                asm volatile("cp.async.commit_group;" ::: "memory");
            }
        }
    }
    epilogue(acc, e, bias3, bias5, sm, m0, n0, l, h, b);
}

__device__ void stats_one(int bc, char* sm){
    const float* p = d_buf_o + (size_t)bc*HH*WW;
    const int tid=threadIdx.x;
    float* smx=(float*)sm; float* ssm=smx+256;
    __syncthreads();
    float mx=-3.4e38f, s=0.f;
    for (int i=tid;i<HH*WW;i+=256){ const float v=__ldcg(p+i); mx=fmaxf(mx,v); s+=v; }
    smx[tid]=mx; ssm[tid]=s; __syncthreads();
    for (int st=128;st>0;st>>=1){
        if (tid<st){ smx[tid]=fmaxf(smx[tid],smx[tid+st]); ssm[tid]+=ssm[tid+st]; }
        __syncthreads();
    }
    if (tid==0){ d_stats[bc]=smx[0]; d_stats[BB*CC+bc]=ssm[0]*(1.f/(HH*WW)); }
}

__device__ __forceinline__ int res_tb(int c){ return (c<10)? c*36 : 360+(c-10)*36; }

// ---------------- the dataflow megakernel ----------------
__global__ __launch_bounds__(256,3) void mega(MegaArgs A, int ncta){
    extern __shared__ char smraw[];
    const uint32_t sb0=smem_u32(smraw), sb=(sb0+127)&~127u;
    char* sm = smraw + (sb-sb0);
    const int tid=threadIdx.x, cid=blockIdx.x;

    unsigned lph=0;
    if (tid==0) lph = g_phase;

    const float SCALE = 1.0f/24.0f;
    __nv_bfloat16* at_x  = d_at[0];
    __nv_bfloat16* at_bo = d_at[1];
    __nv_bfloat16* at_m1 = d_at[2];
    __nv_bfloat16* at_m3 = d_at[3];
    __nv_bfloat16* at_m5 = d_at[4];

    // zero sync state, then one barrier
    {
        uint4* fz=(uint4*)d_flag;
        for (int idx=cid*256+tid; idx<1248; idx+=ncta*256) fz[idx]=make_uint4(0,0,0,0);
        if (cid==0 && tid<46) d_segdone[tid]=0;
        if (cid==0 && tid==0) d_claim=0;
    }
    gridbar(lph, ncta);

    __shared__ unsigned s_u;
    int cg_have = -1;

    for(;;){
        __syncthreads();
        if (tid==0) s_u = atomicAdd(&d_claim, 1u);
        __syncthreads();
        const unsigned u = s_u;
        if (u >= NTOT) break;

        // ---- decode ----
        int kind, r=0, i=0, j=-1;
        if (u < 998){ kind=0; r=(int)u; }
        else if (u < 1510){ kind=1; r=(int)u-998; }
        else {
            unsigned v=u-1510;
            for(;;){ unsigned sz=(c_mfej[i]>=0)?3328u:1024u; if (v<sz) break; v-=sz; i++; }
            j = c_mfej[i];
            if (v<512){ kind=2; r=(int)v; }
            else if (v<1024){ kind=3; r=(int)v-512; }
            else if (v<1536){ kind=4; r=(int)v-1024; }
            else if (v<2048){ kind=5; r=(int)v-1536; }
            else if (v<2560){ kind=6; r=(int)v-2048; }
            else if (v<2816){ kind=7; r=(int)v-2560; }
            else { kind=8; r=(int)v-2816; }
        }
        const int h=r&127, b=r>>7;
        const int lo1 = h>0?h-1:0,  hi1 = h<127?h+1:127;
        const int lo2 = h>1?h-2:0,  hi2 = h<126?h+2:127;

        // ---- wait deps (tid0) ----
        if (tid==0){
            switch(kind){
            case 2:{ wait_cnt(39,998);
                     int inf = (i==0)?0 : (c_mfej[i-1]>=0 ? 34+c_mfej[i-1] : 2+2*(i-1));
                     wait_rows(inf,b,lo1,hi1); } break;
            case 3: wait_rows(1+2*i,b,lo1,hi1); break;
            case 4: wait_cnt(39,998); wait_rows(2+2*i,b,lo1,hi1); break;
            case 5: wait_cnt(39,998); wait_rows(2+2*i,b,lo1,hi1); break;
            case 6: wait_cnt(39,998); wait_rows(2+2*i,b,lo2,hi2); break;
            case 7: wait_cnt(2+2*i,512); break;
            case 8: wait_cnt(40+j,256);
                    wait_rows(19+3*j,b,h,h);
                    wait_rows(20+3*j,b,lo1,hi1);
                    wait_rows(21+3*j,b,lo2,hi2); break;
            default: break;
            }
            __threadfence();
        }
        __syncthreads();

        // ---- execute ----
        int flagid=-1, cntid=-1;
        switch(kind){
        case 0: prep_one(r, A, SCALE); cntid=39; break;
        case 1: ingest_one(h,b,A.x,sm); flagid=0; break;
        case 2:{
            const int c0=i*2;
            Epi e; e.bias=A.resb+(size_t)c0*CC; e.res=nullptr; e.cg=nullptr;
            e.map=nullptr; e.xres=nullptr; e.out=nullptr; e.atout=at_m1; e.act=1;
            const __nv_bfloat16* ain = (i==0)? at_x : at_bo;
            conv_one<3>(h,b, ain, d_wb+(size_t)res_tb(c0)*8192, 9, e, sm, sb);
            flagid=1+2*i; } break;
        case 3:{
            const int c1=i*2+1;
            Epi e; e.bias=A.resb+(size_t)c1*CC; e.res=(i==0)?A.x:d_buf_o; e.cg=nullptr;
            e.map=nullptr; e.xres=nullptr; e.out=d_buf_o; e.atout=at_bo; e.act=0;
            conv_one<3>(h,b, at_m1, d_wb+(size_t)res_tb(c1)*8192, 9, e, sm, sb);
            flagid=2+2*i; cntid=2+2*i; } break;
        case 4:{
            const int ca=j*2;
            Epi e; e.bias=A.mb1+(size_t)ca*CC; e.res=nullptr; e.cg=nullptr;
            e.map=nullptr; e.xres=nullptr; e.out=nullptr; e.atout=at_m1; e.act=2;
            conv_one<1>(h,b, at_bo, d_wb+(size_t)(648+ca)*8192, 0, e, sm, sb);
            flagid=19+3*j; } break;
        case 5:{
            const int ca=j*2;
            Epi e; e.bias=A.mb3+(size_t)ca*CC; e.res=nullptr; e.cg=nullptr;
            e.map=nullptr; e.xres=nullptr; e.out=nullptr; e.atout=at_m3; e.act=2;
            conv_one<3>(h,b, at_bo, d_wb+(size_t)(658+ca*9)*8192, 0, e, sm, sb);
            flagid=20+3*j; } break;
        case 6:{
            const int ca=j*2;
            Epi e; e.bias=A.mb5+(size_t)ca*CC; e.res=nullptr; e.cg=nullptr;
            e.map=nullptr; e.xres=nullptr; e.out=nullptr; e.atout=at_m5; e.act=2;
            conv_one<5>(h,b, at_bo, d_wb+(size_t)(748+ca*25)*8192, 0, e, sm, sb);
            flagid=21+3*j; } break;
        case 7: stats_one(r, sm); cntid=40+j; break;
        case 8:{
            if (cg_have != j){
                __syncthreads();
                {
                    const int bb=tid>>6, c=tid&63;
                    const float* cw1=A.caw1+(size_t)j*4*CC;
                    const float* cw2=A.caw2+(size_t)j*CC*4;
                    float se=0.f;
                    #pragma unroll
                    for (int hh=0;hh<4;hh++){
                        float hm=0.f, ha=0.f;
                        for (int ii=0;ii<CC;ii++){
                            const float wv=cw1[hh*CC+ii];
                            hm+=wv*__ldcg(&d_stats[bb*CC+ii]);
                            ha+=wv*__ldcg(&d_stats[BB*CC+bb*CC+ii]);
                        }
                        se+=cw2[c*4+hh]*(fmaxf(hm,0.f)+fmaxf(ha,0.f));
                    }
                    const float xll=1.f/(1.f+expf(-se));
                    ((float*)(sm+CGOFF))[tid]=
                        A.fcw[j*2+1]*(A.fcw[j*2]*xll+A.fcb[j*2])+A.fcb[j*2+1];
                }
                __syncthreads();
                cg_have = j;
            }
            const int cb=j*2+1;
            Epi e; e.bias=A.mb1+(size_t)cb*CC; e.res=nullptr;
            e.cg=(const float*)(sm+CGOFF);
            e.map=(j==4)?A.map_:nullptr; e.xres=(j==4)?A.x:nullptr;
            e.out=(j==4)?A.out:d_buf_o; e.atout=(j==4)?nullptr:at_bo; e.act=0;
            mfeb_one(h,b, at_m1, at_m3, at_m5,
                     d_wb+(size_t)(648+cb)*8192,
                     d_wb+(size_t)(658+cb*9)*8192,
                     d_wb+(size_t)(748+cb*25)*8192,
                     A.mb3+(size_t)cb*CC, A.mb5+(size_t)cb*CC, e, sm, sb);
            flagid=34+j; } break;
        }

        // ---- publish completion ----
        __syncthreads();
        if (tid==0){
            __threadfence();
            if (flagid>=0) ((volatile unsigned char*)d_flag)[flagid*512 + r] = 1;
            if (cntid>=0)  atomicAdd(&d_segdone[cntid], 1u);
        }
    }
}

extern "C" void kernel_launch(void* const* d_in, const int* in_sizes, int n_in,
                              void* d_out, int out_size)
{
    MegaArgs A;
    A.x    = (const float*)d_in[0];
    A.cf1  = (const float*)d_in[1];
    A.cf2  = (const float*)d_in[2];
    A.map_ = (const float*)d_in[3];
    A.resw = (const float*)d_in[4];
    A.resb = (const float*)d_in[5];
    A.mw1  = (const float*)d_in[6];
    A.mb1  = (const float*)d_in[7];
    A.mw3  = (const float*)d_in[8];
    A.mb3  = (const float*)d_in[9];
    A.mw5  = (const float*)d_in[10];
    A.mb5  = (const float*)d_in[11];
    A.caw1 = (const float*)d_in[12];
    A.caw2 = (const float*)d_in[13];
    A.fcw  = (const float*)d_in[14];
    A.fcb  = (const float*)d_in[15];
    A.out  = (float*)d_out;

    cudaFuncSetAttribute(mega, cudaFuncAttributeMaxDynamicSharedMemorySize, SMEMSZ);

    int dev=0, sms=0, occ=0;
    cudaGetDevice(&dev);
    cudaDeviceGetAttribute(&sms, cudaDevAttrMultiProcessorCount, dev);
    cudaOccupancyMaxActiveBlocksPerMultiprocessor(&occ, mega, 256, SMEMSZ);
    if (occ < 1) occ = 1;
    int ncta = sms * occ;
    if (ncta < 1) ncta = 1;
    if (ncta > 512) ncta = 512;

    mega<<<ncta, 256, SMEMSZ>>>(A, ncta);
}

// round 16
// speedup vs baseline: 1.1771x; 1.1771x over previous
#include <cuda_runtime.h>
#include <cuda_bf16.h>
#include <stdint.h>

#define BB 4
#define CC 64
#define HH 128
#define WW 128
#define NTOT 22246u

// ---------------- scratch (__device__ globals: allocation-free) ----------------
__device__ float d_buf_o[BB*CC*HH*WW];
__device__ float d_stats[2*BB*CC];
__device__ __align__(128) __nv_bfloat16 d_wb[998ull*8192];
// atiles: 0:x 1:bo 2:m1/mid 3:m3 4:m5
__device__ __align__(128) __nv_bfloat16 d_at[5][(size_t)BB*HH*16384];

__device__ volatile unsigned g_phase;
__device__ unsigned g_cnt;
__device__ unsigned d_claim;
__device__ unsigned d_segdone[46];
__device__ unsigned char d_flag[39*512];

__constant__ int c_mfej[9] = {-1,0,-1,1,-1,2,-1,3,4};

struct MegaArgs {
    const float *x,*cf1,*cf2,*map_,*resw,*resb,*mw1,*mb1,*mw3,*mb3,*mw5,*mb5,
                *caw1,*caw2,*fcw,*fcb;
    float* out;
};
struct Epi {
    const float *bias,*res,*cg,*map,*xres;
    float* out;
    __nv_bfloat16* atout;
    int act;
};

// smem layout (single A buffer, double B, cg slot)
#define WPU 132
#define ALO (WPU*128)
#define ASZ (WPU*256)
#define BOFF ASZ
#define CGOFF (BOFF+32768)
#define SMEMSZ (CGOFF+1024+128)

// ---------------- helpers ----------------
__device__ __forceinline__ uint32_t smem_u32(const void* p){
    uint32_t a;
    asm("{ .reg .u64 t; cvta.to.shared.u64 t, %1; cvt.u32.u64 %0, t; }":"=r"(a):"l"(p));
    return a;
}
#define LDSM4(r, a) \
    asm volatile("ldmatrix.sync.aligned.m8n8.x4.shared.b16 {%0,%1,%2,%3}, [%4];" \
        : "=r"((r)[0]),"=r"((r)[1]),"=r"((r)[2]),"=r"((r)[3]) : "r"(a))

__device__ __forceinline__ void mma16816(float* c, const uint32_t* a,
                                         uint32_t b0, uint32_t b1){
    asm volatile("mma.sync.aligned.m16n8k16.row.col.f32.bf16.bf16.f32 "
        "{%0,%1,%2,%3}, {%4,%5,%6,%7}, {%8,%9}, {%0,%1,%2,%3};"
        : "+f"(c[0]),"+f"(c[1]),"+f"(c[2]),"+f"(c[3])
        : "r"(a[0]),"r"(a[1]),"r"(a[2]),"r"(a[3]), "r"(b0),"r"(b1));
}
__device__ __forceinline__ void split_pack(float v0, float v1, uint32_t& hp, uint32_t& lp){
    const __nv_bfloat16 h0=__float2bfloat16(v0), h1=__float2bfloat16(v1);
    const __nv_bfloat16 l0=__float2bfloat16(v0-__bfloat162float(h0));
    const __nv_bfloat16 l1=__float2bfloat16(v1-__bfloat162float(h1));
    hp = (uint32_t)__bfloat16_as_ushort(h0) | ((uint32_t)__bfloat16_as_ushort(h1)<<16);
    lp = (uint32_t)__bfloat16_as_ushort(l0) | ((uint32_t)__bfloat16_as_ushort(l1)<<16);
}

// ---------------- grid barrier (one use: after zeroing sync state) ----------------
__device__ __forceinline__ void gridbar(unsigned& lph, int ncta){
    __syncthreads();
    if (threadIdx.x==0){
        const unsigned target = ++lph;
        __threadfence();
        if (atomicAdd(&g_cnt,1u) == (unsigned)ncta-1u){
            atomicExch(&g_cnt, 0u);
            __threadfence();
            g_phase = target;
        } else {
            while (g_phase < target) __nanosleep(64);
        }
        __threadfence();
    }
    __syncthreads();
}

// ---------------- dep waits (tid0 only) ----------------
__device__ __forceinline__ void wait_rows(int f, int b, int lo, int hi){
    volatile unsigned char* fl = d_flag + f*512 + b*128;
    for (int r=lo; r<=hi; r++) while (fl[r]==0) __nanosleep(64);
}
__device__ __forceinline__ void wait_cnt(int s, unsigned n){
    volatile unsigned* p = (volatile unsigned*)&d_segdone[s];
    while (*p < n) __nanosleep(64);
}

// ---------------- weight prep ----------------
__device__ void prep_one(int tile, const MegaArgs& A, float SCALE){
    const float* src; const float* cp = nullptr; float scale = 1.f; int k2, tap;
    if (tile < 360){
        const int conv = tile/36, rem = tile%36, b = rem/9;
        tap = rem%9; k2 = 9; scale = SCALE;
        src = A.resw + (size_t)conv*CC*CC*9;
        cp  = A.cf1 + (size_t)(conv*4 + b)*CC;
    } else if (tile < 648){
        const int t = tile-360, conv = t/36, rem = t%36, b = rem/9;
        tap = rem%9; k2 = 9; scale = SCALE;
        src = A.resw + (size_t)(10+conv)*CC*CC*9;
        cp  = A.cf2 + (size_t)(conv*4 + b)*CC;
    } else if (tile < 658){
        const int c = tile-648;
        tap = 0; k2 = 1;
        src = A.mw1 + (size_t)c*CC*CC;
    } else if (tile < 748){
        const int t = tile-658, conv = t/9;
        tap = t%9; k2 = 9;
        src = A.mw3 + (size_t)conv*CC*CC*9;
    } else {
        const int t = tile-748, conv = t/25;
        tap = t%25; k2 = 25;
        src = A.mw5 + (size_t)conv*CC*CC*25;
    }
    __nv_bfloat16* dst = d_wb + (size_t)tile*8192;
    for (int e=threadIdx.x; e<4096; e+=256){
        const int oc=e>>6, ic=e&63;
        float v = src[(size_t)(oc*CC+ic)*k2 + tap]*scale;
        if (cp) v *= cp[ic];
        const __nv_bfloat16 hb=__float2bfloat16(v);
        const __nv_bfloat16 lb=__float2bfloat16(v-__bfloat162float(hb));
        const uint32_t off=(uint32_t)oc*128+(uint32_t)ic*2;
        const uint32_t sw=off^((off>>3)&0x70);
        dst[sw>>1]=hb;
        dst[4096+(sw>>1)]=lb;
    }
}

// ---------------- ingest one (b,h) row of x ----------------
__device__ void ingest_one(int h, int b, const float* x, char* sm){
    float* raw = (float*)sm;
    char*  at  = sm + BOFF;
    const int tid=threadIdx.x;
    __syncthreads();
    for (int i=tid;i<CC*WW;i+=256){
        const int ic=i>>7, w=i&127;
        raw[i] = x[(((size_t)b*CC+ic)*HH+h)*WW + w];
    }
    __syncthreads();
    const int w=tid&127, half=tid>>7;
    #pragma unroll
    for (int k=0;k<16;k++){
        const int ic=half*32+2*k;
        uint32_t hp, lp;
        split_pack(raw[ic*WW+w], raw[(ic+1)*WW+w], hp, lp);
        const uint32_t ro = (uint32_t)w*128 + ((uint32_t)((ic>>3)^(w&7))<<4) + (uint32_t)(ic&7)*2;
        *(uint32_t*)(at + ro) = hp;
        *(uint32_t*)(at + 16384 + ro) = lp;
    }
    __syncthreads();
    uint4* dst=(uint4*)(d_at[0] + (size_t)(b*HH+h)*16384);
    const uint4* src=(const uint4*)at;
    #pragma unroll
    for (int j=0;j<8;j++) dst[tid+j*256]=src[tid+j*256];
}

// ---------------- conv machinery ----------------
__device__ __forceinline__ void zero_pads1(char* sm){
    const int tid=threadIdx.x;
    if (tid<64){
        const int plane=tid>>5, r=(tid>>3)&3, c=tid&7;
        const int row=(r<2)? r : (128+r);
        ((uint4*)(sm + plane*ALO + row*128))[c]=make_uint4(0,0,0,0);
    }
}
// A (atile) loads: .cg — atiles are rewritten cross-SM; L1 must be bypassed
__device__ __forceinline__ void issueA1(uint32_t sb, const char* abase, int arow){
    const int tid=threadIdx.x;
    const int sz=(arow>=0 && arow<HH)?16:0;
    const int rc=arow<0?0:(arow>127?127:arow);
    const char* src=abase+(size_t)rc*32768;
    const uint32_t d0=sb + 2*128;
    #pragma unroll
    for (int j=0;j<4;j++){
        const int c=tid+j*256;
        asm volatile("cp.async.cg.shared.global [%0], [%1], 16, %2;"
            :: "r"(d0+c*16), "l"(src+c*16), "r"(sz) : "memory");
        asm volatile("cp.async.cg.shared.global [%0], [%1], 16, %2;"
            :: "r"(d0+ALO+c*16), "l"(src+16384+c*16), "r"(sz) : "memory");
    }
}
// B (weights) loads: .cg — R15 showed .ca thrashes the tiny L1 carveout
__device__ __forceinline__ void issueB(uint32_t sb, const __nv_bfloat16* bptr, int buf){
    const int tid=threadIdx.x;
    const char* src=(const char*)bptr;
    const uint32_t d0=sb+BOFF+(uint32_t)buf*16384;
    #pragma unroll
    for (int j=0;j<4;j++){
        const int c=tid+j*256;
        asm volatile("cp.async.cg.shared.global [%0], [%1], 16;"
            :: "r"(d0+c*16), "l"(src+c*16) : "memory");
    }
}

__device__ __forceinline__ void do_tap2(float acc[2][4][4], uint32_t aB, uint32_t bB,
                                        int s, int m0, int n0, int l){
    #pragma unroll
    for (int ks=0;ks<4;ks++){
        const int ch = ks*2 + (l>>4);
        uint32_t ah[2][4], al[2][4], bh[2][4], bl[2][4];
        #pragma unroll
        for (int mt=0;mt<2;mt++){
            const int row = m0+mt*16+s+(l&15);
            const uint32_t ad = aB + (uint32_t)row*128 + ((uint32_t)(ch ^ ((row-2)&7))<<4);
            LDSM4(ah[mt], ad);
            LDSM4(al[mt], ad + ALO);
        }
        #pragma unroll
        for (int np=0;np<2;np++){
            const int row = n0+np*16+(l&15);
            const uint32_t bd = bB + (uint32_t)row*128 + ((uint32_t)(ch ^ (row&7))<<4);
            LDSM4(bh[np], bd);
            LDSM4(bl[np], bd + 8192);
        }
        #pragma unroll
        for (int mt=0;mt<2;mt++)
            #pragma unroll
            for (int np=0;np<2;np++)
                #pragma unroll
                for (int q=0;q<2;q++)
                    mma16816(acc[mt][np*2+q], ah[mt], bh[np][q], bh[np][2+q]);
        #pragma unroll
        for (int mt=0;mt<2;mt++)
            #pragma unroll
            for (int np=0;np<2;np++)
                #pragma unroll
                for (int q=0;q<2;q++)
                    mma16816(acc[mt][np*2+q], al[mt], bh[np][q], bh[np][2+q]);
        #pragma unroll
        for (int mt=0;mt<2;mt++)
            #pragma unroll
            for (int np=0;np<2;np++)
                #pragma unroll
                for (int q=0;q<2;q++)
                    mma16816(acc[mt][np*2+q], ah[mt], bl[np][q], bl[np][2+q]);
    }
}

__device__ void epilogue(float acc[2][4][4], const Epi& e,
                         const float* bias3, const float* bias5,
                         char* sm, int m0, int n0, int l, int h, int b){
    const int tid=threadIdx.x;
    __syncthreads();
    float* os=(float*)sm;
    #pragma unroll
    for (int mt=0;mt<2;mt++)
        #pragma unroll
        for (int nt=0;nt<4;nt++)
            #pragma unroll
            for (int q=0;q<4;q++){
                const int row=m0+mt*16+(l>>2)+((q>>1)<<3);
                const int col=n0+nt*8+((l&3)<<1)+(q&1);
                os[row*65+col]=acc[mt][nt][q];
            }
    __syncthreads();

    const int w=tid&127, oc0=(tid>>7)*32;
    const size_t pix=(size_t)h*WW+w;
    const float mv = e.map? e.map[(size_t)b*HH*WW+pix] : 0.f;
    char* smA2 = sm + BOFF;
    #pragma unroll 4
    for (int k=0;k<32;k+=2){
        float vv[2];
        #pragma unroll
        for (int s2=0;s2<2;s2++){
            const int oc=oc0+k+s2;
            const size_t idx=((size_t)(b*CC+oc))*HH*WW+pix;
            float v=os[w*65+oc];
            if (e.bias) v+=e.bias[oc];
            if (bias3)  v+=bias3[oc];
            if (bias5)  v+=bias5[oc];
            if (e.act==1)      v=fmaxf(v,0.f);
            else if (e.act==2) v=(v>0.f)?v:0.01f*v;
            if (e.res) v+=__ldcg(e.res+idx);
            if (e.cg)  v*=e.cg[b*CC+oc];
            if (e.map) v=v*mv+e.xres[idx];
            if (e.out) e.out[idx]=v;
            vv[s2]=v;
        }
        if (e.atout){
            const int oc=oc0+k;
            uint32_t hp, lp;
            split_pack(vv[0], vv[1], hp, lp);
            const uint32_t ro = (uint32_t)w*128 + ((uint32_t)((oc>>3)^(w&7))<<4)
                              + (uint32_t)(oc&7)*2;
            *(uint32_t*)(smA2 + ro) = hp;
            *(uint32_t*)(smA2 + 16384 + ro) = lp;
        }
    }
    if (e.atout){
        __syncthreads();
        uint4* dst=(uint4*)(e.atout + (size_t)(b*HH+h)*16384);
        const uint4* src=(const uint4*)smA2;
        #pragma unroll
        for (int j=0;j<8;j++) dst[tid+j*256]=src[tid+j*256];
    }
}

template<int KD>
__device__ void conv_one(int h, int b, const __nv_bfloat16* ain,
                         const __nv_bfloat16* wt, int bstride,
                         const Epi& e, char* sm, uint32_t sb){
    constexpr int PAD=KD/2, TAPS=KD*KD;
    const int tid=threadIdx.x, l=tid&31, wid=tid>>5;
    const int m0=(wid&3)*32, n0=(wid>>2)*32;

    __syncthreads();
    zero_pads1(sm);
    const char* abase=(const char*)ain + (size_t)b*HH*32768;

    float acc[2][4][4];
    #pragma unroll
    for (int mt=0;mt<2;mt++)
        #pragma unroll
        for (int nt=0;nt<4;nt++)
            #pragma unroll
            for (int q=0;q<4;q++) acc[mt][nt][q]=0.f;

    issueA1(sb, abase, h-PAD);
    issueB(sb, wt + (size_t)b*bstride*8192, 0);
    asm volatile("cp.async.commit_group;" ::: "memory");

    int kh=0, kw=0;
    for (int t=0;t<TAPS;t++){
        asm volatile("cp.async.wait_group 0;" ::: "memory");
        __syncthreads();
        if (t+1<TAPS){
            issueB(sb, wt + ((size_t)b*bstride + t+1)*8192, (t+1)&1);
            asm volatile("cp.async.commit_group;" ::: "memory");
        }
        do_tap2(acc, sb, sb+BOFF+(uint32_t)(t&1)*16384, 2+kw-PAD, m0, n0, l);
        kw++; if (kw==KD){kw=0; kh++;}
        if (t+1<TAPS && kw==0){
            __syncthreads();
            issueA1(sb, abase, h+kh-PAD);
            asm volatile("cp.async.commit_group;" ::: "memory");
        }
    }
    epilogue(acc, e, nullptr, nullptr, sm, m0, n0, l, h, b);
}

__device__ void mfeb_one(int h, int b,
                         const __nv_bfloat16* a1, const __nv_bfloat16* a3, const __nv_bfloat16* a5,
                         const __nv_bfloat16* w1, const __nv_bfloat16* w3, const __nv_bfloat16* w5,
                         const float* bias3, const float* bias5, const Epi& e,
                         char* sm, uint32_t sb){
    const int tid=threadIdx.x, l=tid&31, wid=tid>>5;
    const int m0=(wid&3)*32, n0=(wid>>2)*32;

    __syncthreads();
    zero_pads1(sm);
    const char* ab3=(const char*)a3 + (size_t)b*HH*32768;
    const char* ab5=(const char*)a5 + (size_t)b*HH*32768;

    float acc[2][4][4];
    #pragma unroll
    for (int mt=0;mt<2;mt++)
        #pragma unroll
        for (int nt=0;nt<4;nt++)
            #pragma unroll
            for (int q=0;q<4;q++) acc[mt][nt][q]=0.f;

    issueA1(sb, (const char*)a1 + (size_t)b*HH*32768, h);
    issueB(sb, w1, 0);
    asm volatile("cp.async.commit_group;" ::: "memory");

    for (int t=0;t<35;t++){
        asm volatile("cp.async.wait_group 0;" ::: "memory");
        __syncthreads();
        if (t<34){
            const int tn=t+1;
            const __nv_bfloat16* bp = (tn<10)? w3 + (size_t)(tn-1)*8192
                                             : w5 + (size_t)(tn-10)*8192;
            issueB(sb, bp, tn&1);
            asm volatile("cp.async.commit_group;" ::: "memory");
        }
        const int s = (t==0)? 2 : (t<10)? 1+(t-1)%3 : (t-10)%5;
        do_tap2(acc, sb, sb+BOFF+(uint32_t)(t&1)*16384, s, m0, n0, l);
        if (t<34){
            const int tn=t+1;
            bool rel; const char* asrc; int arow;
            if (tn<10){ const int u=tn-1; rel=(u%3==0); asrc=ab3; arow=h+u/3-1; }
            else      { const int u=tn-10; rel=(u%5==0); asrc=ab5; arow=h+u/5-2; }
            if (rel){
                __syncthreads();
                issueA1(sb, asrc, arow);
                asm volatile("cp.async.commit_group;" ::: "memory");
            }
        }
    }
    epilogue(acc, e, bias3, bias5, sm, m0, n0, l, h, b);
}

__device__ void stats_one(int bc, char* sm){
    const float* p = d_buf_o + (size_t)bc*HH*WW;
    const int tid=threadIdx.x;
    float* smx=(float*)sm; float* ssm=smx+256;
    __syncthreads();
    float mx=-3.4e38f, s=0.f;
    for (int i=tid;i<HH*WW;i+=256){ const float v=__ldcg(p+i); mx=fmaxf(mx,v); s+=v; }
    smx[tid]=mx; ssm[tid]=s; __syncthreads();
    for (int st=128;st>0;st>>=1){
        if (tid<st){ smx[tid]=fmaxf(smx[tid],smx[tid+st]); ssm[tid]+=ssm[tid+st]; }
        __syncthreads();
    }
    if (tid==0){ d_stats[bc]=smx[0]; d_stats[BB*CC+bc]=ssm[0]*(1.f/(HH*WW)); }
}

__device__ __forceinline__ int res_tb(int c){ return (c<10)? c*36 : 360+(c-10)*36; }

// ---------------- the dataflow megakernel (dual-claim) ----------------
__global__ __launch_bounds__(256,3) void mega(MegaArgs A, int ncta){
    extern __shared__ char smraw[];
    const uint32_t sb0=smem_u32(smraw), sb=(sb0+127)&~127u;
    char* sm = smraw + (sb-sb0);
    const int tid=threadIdx.x, cid=blockIdx.x;

    unsigned lph=0;
    if (tid==0) lph = g_phase;

    const float SCALE = 1.0f/24.0f;
    __nv_bfloat16* at_x  = d_at[0];
    __nv_bfloat16* at_bo = d_at[1];
    __nv_bfloat16* at_m1 = d_at[2];
    __nv_bfloat16* at_m3 = d_at[3];
    __nv_bfloat16* at_m5 = d_at[4];

    // zero sync state, then one barrier
    {
        uint4* fz=(uint4*)d_flag;
        for (int idx=cid*256+tid; idx<1248; idx+=ncta*256) fz[idx]=make_uint4(0,0,0,0);
        if (cid==0 && tid<46) d_segdone[tid]=0;
        if (cid==0 && tid==0) d_claim=0;
    }
    gridbar(lph, ncta);

    __shared__ unsigned s_u;
    int cg_have = -1;

    for(;;){
        __syncthreads();
        if (tid==0) s_u = atomicAdd(&d_claim, 2u);
        __syncthreads();
        const unsigned u0 = s_u;
        if (u0 >= NTOT) break;

        for (int kk=0; kk<2; kk++){
            const unsigned u = u0 + (unsigned)kk;
            if (u >= NTOT) break;

            // ---- decode ----
            int kind, r=0, i=0, j=-1;
            if (u < 998){ kind=0; r=(int)u; }
            else if (u < 1510){ kind=1; r=(int)u-998; }
            else {
                unsigned v=u-1510;
                for(;;){ unsigned sz=(c_mfej[i]>=0)?3328u:1024u; if (v<sz) break; v-=sz; i++; }
                j = c_mfej[i];
                if (v<512){ kind=2; r=(int)v; }
                else if (v<1024){ kind=3; r=(int)v-512; }
                else if (v<1536){ kind=4; r=(int)v-1024; }
                else if (v<2048){ kind=5; r=(int)v-1536; }
                else if (v<2560){ kind=6; r=(int)v-2048; }
                else if (v<2816){ kind=7; r=(int)v-2560; }
                else { kind=8; r=(int)v-2816; }
            }
            const int h=r&127, b=r>>7;
            const int lo1 = h>0?h-1:0,  hi1 = h<127?h+1:127;
            const int lo2 = h>1?h-2:0,  hi2 = h<126?h+2:127;

            // ---- wait deps (tid0) ----
            if (tid==0){
                switch(kind){
                case 2:{ wait_cnt(39,998);
                         int inf = (i==0)?0 : (c_mfej[i-1]>=0 ? 34+c_mfej[i-1] : 2+2*(i-1));
                         wait_rows(inf,b,lo1,hi1); } break;
                case 3: wait_rows(1+2*i,b,lo1,hi1); break;
                case 4: wait_cnt(39,998); wait_rows(2+2*i,b,lo1,hi1); break;
                case 5: wait_cnt(39,998); wait_rows(2+2*i,b,lo1,hi1); break;
                case 6: wait_cnt(39,998); wait_rows(2+2*i,b,lo2,hi2); break;
                case 7: wait_cnt(2+2*i,512); break;
                case 8: wait_cnt(40+j,256);
                        wait_rows(19+3*j,b,h,h);
                        wait_rows(20+3*j,b,lo1,hi1);
                        wait_rows(21+3*j,b,lo2,hi2); break;
                default: break;
                }
                __threadfence();
            }
            __syncthreads();

            // ---- execute ----
            int flagid=-1, cntid=-1;
            switch(kind){
            case 0: prep_one(r, A, SCALE); cntid=39; break;
            case 1: ingest_one(h,b,A.x,sm); flagid=0; break;
            case 2:{
                const int c0=i*2;
                Epi e; e.bias=A.resb+(size_t)c0*CC; e.res=nullptr; e.cg=nullptr;
                e.map=nullptr; e.xres=nullptr; e.out=nullptr; e.atout=at_m1; e.act=1;
                const __nv_bfloat16* ain = (i==0)? at_x : at_bo;
                conv_one<3>(h,b, ain, d_wb+(size_t)res_tb(c0)*8192, 9, e, sm, sb);
                flagid=1+2*i; } break;
            case 3:{
                const int c1=i*2+1;
                Epi e; e.bias=A.resb+(size_t)c1*CC; e.res=(i==0)?A.x:d_buf_o; e.cg=nullptr;
                e.map=nullptr; e.xres=nullptr; e.out=d_buf_o; e.atout=at_bo; e.act=0;
                conv_one<3>(h,b, at_m1, d_wb+(size_t)res_tb(c1)*8192, 9, e, sm, sb);
                flagid=2+2*i; cntid=2+2*i; } break;
            case 4:{
                const int ca=j*2;
                Epi e; e.bias=A.mb1+(size_t)ca*CC; e.res=nullptr; e.cg=nullptr;
                e.map=nullptr; e.xres=nullptr; e.out=nullptr; e.atout=at_m1; e.act=2;
                conv_one<1>(h,b, at_bo, d_wb+(size_t)(648+ca)*8192, 0, e, sm, sb);
                flagid=19+3*j; } break;
            case 5:{
                const int ca=j*2;
                Epi e; e.bias=A.mb3+(size_t)ca*CC; e.res=nullptr; e.cg=nullptr;
                e.map=nullptr; e.xres=nullptr; e.out=nullptr; e.atout=at_m3; e.act=2;
                conv_one<3>(h,b, at_bo, d_wb+(size_t)(658+ca*9)*8192, 0, e, sm, sb);
                flagid=20+3*j; } break;
            case 6:{
                const int ca=j*2;
                Epi e; e.bias=A.mb5+(size_t)ca*CC; e.res=nullptr; e.cg=nullptr;
                e.map=nullptr; e.xres=nullptr; e.out=nullptr; e.atout=at_m5; e.act=2;
                conv_one<5>(h,b, at_bo, d_wb+(size_t)(748+ca*25)*8192, 0, e, sm, sb);
                flagid=21+3*j; } break;
            case 7: stats_one(r, sm); cntid=40+j; break;
            case 8:{
                if (cg_have != j){
                    __syncthreads();
                    {
                        const int bb=tid>>6, c=tid&63;
                        const float* cw1=A.caw1+(size_t)j*4*CC;
                        const float* cw2=A.caw2+(size_t)j*CC*4;
                        float se=0.f;
                        #pragma unroll
                        for (int hh=0;hh<4;hh++){
                            float hm=0.f, ha=0.f;
                            for (int ii=0;ii<CC;ii++){
                                const float wv=cw1[hh*CC+ii];
                                hm+=wv*__ldcg(&d_stats[bb*CC+ii]);
                                ha+=wv*__ldcg(&d_stats[BB*CC+bb*CC+ii]);
                            }
                            se+=cw2[c*4+hh]*(fmaxf(hm,0.f)+fmaxf(ha,0.f));
                        }
                        const float xll=1.f/(1.f+expf(-se));
                        ((float*)(sm+CGOFF))[tid]=
                            A.fcw[j*2+1]*(A.fcw[j*2]*xll+A.fcb[j*2])+A.fcb[j*2+1];
                    }
                    __syncthreads();
                    cg_have = j;
                }
                const int cb=j*2+1;
                Epi e; e.bias=A.mb1+(size_t)cb*CC; e.res=nullptr;
                e.cg=(const float*)(sm+CGOFF);
                e.map=(j==4)?A.map_:nullptr; e.xres=(j==4)?A.x:nullptr;
                e.out=(j==4)?A.out:d_buf_o; e.atout=(j==4)?nullptr:at_bo; e.act=0;
                mfeb_one(h,b, at_m1, at_m3, at_m5,
                         d_wb+(size_t)(648+cb)*8192,
                         d_wb+(size_t)(658+cb*9)*8192,
                         d_wb+(size_t)(748+cb*25)*8192,
                         A.mb3+(size_t)cb*CC, A.mb5+(size_t)cb*CC, e, sm, sb);
                flagid=34+j; } break;
            }

            // ---- publish completion ----
            __syncthreads();
            if (tid==0){
                __threadfence();
                if (flagid>=0) ((volatile unsigned char*)d_flag)[flagid*512 + r] = 1;
                if (cntid>=0)  atomicAdd(&d_segdone[cntid], 1u);
            }
        }
    }
}

extern "C" void kernel_launch(void* const* d_in, const int* in_sizes, int n_in,
                              void* d_out, int out_size)
{
    MegaArgs A;
    A.x    = (const float*)d_in[0];
    A.cf1  = (const float*)d_in[1];
    A.cf2  = (const float*)d_in[2];
    A.map_ = (const float*)d_in[3];
    A.resw = (const float*)d_in[4];
    A.resb = (const float*)d_in[5];
    A.mw1  = (const float*)d_in[6];
    A.mb1  = (const float*)d_in[7];
    A.mw3  = (const float*)d_in[8];
    A.mb3  = (const float*)d_in[9];
    A.mw5  = (const float*)d_in[10];
    A.mb5  = (const float*)d_in[11];
    A.caw1 = (const float*)d_in[12];
    A.caw2 = (const float*)d_in[13];
    A.fcw  = (const float*)d_in[14];
    A.fcb  = (const float*)d_in[15];
    A.out  = (float*)d_out;

    cudaFuncSetAttribute(mega, cudaFuncAttributeMaxDynamicSharedMemorySize, SMEMSZ);

    int dev=0, sms=0, occ=0;
    cudaGetDevice(&dev);
    cudaDeviceGetAttribute(&sms, cudaDevAttrMultiProcessorCount, dev);
    cudaOccupancyMaxActiveBlocksPerMultiprocessor(&occ, mega, 256, SMEMSZ);
    if (occ < 1) occ = 1;
    int ncta = sms * occ;
    if (ncta < 1) ncta = 1;
    if (ncta > 512) ncta = 512;

    mega<<<ncta, 256, SMEMSZ>>>(A, ncta);
}

// round 17
// speedup vs baseline: 1.6058x; 1.3643x over previous
#include <cuda_runtime.h>
#include <cuda_bf16.h>
#include <stdint.h>

#define BB 4
#define CC 64
#define HH 128
#define WW 128
#define NTOT 22246u

// ---------------- scratch (__device__ globals: allocation-free) ----------------
__device__ float d_buf_o[BB*CC*HH*WW];
__device__ float d_stats[2*BB*CC];
__device__ __align__(128) __nv_bfloat16 d_wb[998ull*8192];
// atiles: 0:x 1:bo 2:m1/mid 3:m3 4:m5
__device__ __align__(128) __nv_bfloat16 d_at[5][(size_t)BB*HH*16384];

__device__ volatile unsigned g_phase;
__device__ unsigned g_cnt;
__device__ unsigned d_claim;
__device__ unsigned d_segdone[46];
__device__ unsigned char d_flag[39*512];

__constant__ int c_mfej[9] = {-1,0,-1,1,-1,2,-1,3,4};

struct MegaArgs {
    const float *x,*cf1,*cf2,*map_,*resw,*resb,*mw1,*mb1,*mw3,*mb3,*mw5,*mb5,
                *caw1,*caw2,*fcw,*fcb;
    float* out;
};
struct Epi {
    const float *bias,*res,*cg,*map,*xres;
    float* out;
    __nv_bfloat16* atout;
    int act;
};

// smem layout (single A buffer, double B, cg slot)
#define WPU 132
#define ALO (WPU*128)
#define ASZ (WPU*256)
#define BOFF ASZ
#define CGOFF (BOFF+32768)
#define SMEMSZ (CGOFF+1024+128)

// ---------------- helpers ----------------
__device__ __forceinline__ uint32_t smem_u32(const void* p){
    uint32_t a;
    asm("{ .reg .u64 t; cvta.to.shared.u64 t, %1; cvt.u32.u64 %0, t; }":"=r"(a):"l"(p));
    return a;
}
#define LDSM4(r, a) \
    asm volatile("ldmatrix.sync.aligned.m8n8.x4.shared.b16 {%0,%1,%2,%3}, [%4];" \
        : "=r"((r)[0]),"=r"((r)[1]),"=r"((r)[2]),"=r"((r)[3]) : "r"(a))

__device__ __forceinline__ void mma16816(float* c, const uint32_t* a,
                                         uint32_t b0, uint32_t b1){
    asm volatile("mma.sync.aligned.m16n8k16.row.col.f32.bf16.bf16.f32 "
        "{%0,%1,%2,%3}, {%4,%5,%6,%7}, {%8,%9}, {%0,%1,%2,%3};"
        : "+f"(c[0]),"+f"(c[1]),"+f"(c[2]),"+f"(c[3])
        : "r"(a[0]),"r"(a[1]),"r"(a[2]),"r"(a[3]), "r"(b0),"r"(b1));
}
__device__ __forceinline__ void split_pack(float v0, float v1, uint32_t& hp, uint32_t& lp){
    const __nv_bfloat16 h0=__float2bfloat16(v0), h1=__float2bfloat16(v1);
    const __nv_bfloat16 l0=__float2bfloat16(v0-__bfloat162float(h0));
    const __nv_bfloat16 l1=__float2bfloat16(v1-__bfloat162float(h1));
    hp = (uint32_t)__bfloat16_as_ushort(h0) | ((uint32_t)__bfloat16_as_ushort(h1)<<16);
    lp = (uint32_t)__bfloat16_as_ushort(l0) | ((uint32_t)__bfloat16_as_ushort(l1)<<16);
}

// ---------------- grid barrier (one use: after zeroing sync state) ----------------
__device__ __forceinline__ void gridbar(unsigned& lph, int ncta){
    __syncthreads();
    if (threadIdx.x==0){
        const unsigned target = ++lph;
        __threadfence();
        if (atomicAdd(&g_cnt,1u) == (unsigned)ncta-1u){
            atomicExch(&g_cnt, 0u);
            __threadfence();
            g_phase = target;
        } else {
            while (g_phase < target) __nanosleep(64);
        }
        __threadfence();
    }
    __syncthreads();
}

// ---------------- dep waits (tid0 only) ----------------
__device__ __forceinline__ void wait_rows(int f, int b, int lo, int hi){
    volatile unsigned char* fl = d_flag + f*512 + b*128;
    for (int r=lo; r<=hi; r++) while (fl[r]==0) __nanosleep(64);
}
__device__ __forceinline__ void wait_cnt(int s, unsigned n){
    volatile unsigned* p = (volatile unsigned*)&d_segdone[s];
    while (*p < n) __nanosleep(64);
}

// ---------------- weight prep ----------------
__device__ void prep_one(int tile, const MegaArgs& A, float SCALE){
    const float* src; const float* cp = nullptr; float scale = 1.f; int k2, tap;
    if (tile < 360){
        const int conv = tile/36, rem = tile%36, b = rem/9;
        tap = rem%9; k2 = 9; scale = SCALE;
        src = A.resw + (size_t)conv*CC*CC*9;
        cp  = A.cf1 + (size_t)(conv*4 + b)*CC;
    } else if (tile < 648){
        const int t = tile-360, conv = t/36, rem = t%36, b = rem/9;
        tap = rem%9; k2 = 9; scale = SCALE;
        src = A.resw + (size_t)(10+conv)*CC*CC*9;
        cp  = A.cf2 + (size_t)(conv*4 + b)*CC;
    } else if (tile < 658){
        const int c = tile-648;
        tap = 0; k2 = 1;
        src = A.mw1 + (size_t)c*CC*CC;
    } else if (tile < 748){
        const int t = tile-658, conv = t/9;
        tap = t%9; k2 = 9;
        src = A.mw3 + (size_t)conv*CC*CC*9;
    } else {
        const int t = tile-748, conv = t/25;
        tap = t%25; k2 = 25;
        src = A.mw5 + (size_t)conv*CC*CC*25;
    }
    __nv_bfloat16* dst = d_wb + (size_t)tile*8192;
    for (int e=threadIdx.x; e<4096; e+=256){
        const int oc=e>>6, ic=e&63;
        float v = src[(size_t)(oc*CC+ic)*k2 + tap]*scale;
        if (cp) v *= cp[ic];
        const __nv_bfloat16 hb=__float2bfloat16(v);
        const __nv_bfloat16 lb=__float2bfloat16(v-__bfloat162float(hb));
        const uint32_t off=(uint32_t)oc*128+(uint32_t)ic*2;
        const uint32_t sw=off^((off>>3)&0x70);
        dst[sw>>1]=hb;
        dst[4096+(sw>>1)]=lb;
    }
}

// ---------------- ingest one (b,h) row of x ----------------
__device__ void ingest_one(int h, int b, const float* x, char* sm){
    float* raw = (float*)sm;
    char*  at  = sm + BOFF;
    const int tid=threadIdx.x;
    __syncthreads();
    for (int i=tid;i<CC*WW;i+=256){
        const int ic=i>>7, w=i&127;
        raw[i] = x[(((size_t)b*CC+ic)*HH+h)*WW + w];
    }
    __syncthreads();
    const int w=tid&127, half=tid>>7;
    #pragma unroll
    for (int k=0;k<16;k++){
        const int ic=half*32+2*k;
        uint32_t hp, lp;
        split_pack(raw[ic*WW+w], raw[(ic+1)*WW+w], hp, lp);
        const uint32_t ro = (uint32_t)w*128 + ((uint32_t)((ic>>3)^(w&7))<<4) + (uint32_t)(ic&7)*2;
        *(uint32_t*)(at + ro) = hp;
        *(uint32_t*)(at + 16384 + ro) = lp;
    }
    __syncthreads();
    uint4* dst=(uint4*)(d_at[0] + (size_t)(b*HH+h)*16384);
    const uint4* src=(const uint4*)at;
    #pragma unroll
    for (int j=0;j<8;j++) dst[tid+j*256]=src[tid+j*256];
}

// ---------------- conv machinery ----------------
__device__ __forceinline__ void zero_pads1(char* sm){
    const int tid=threadIdx.x;
    if (tid<64){
        const int plane=tid>>5, r=(tid>>3)&3, c=tid&7;
        const int row=(r<2)? r : (128+r);
        ((uint4*)(sm + plane*ALO + row*128))[c]=make_uint4(0,0,0,0);
    }
}
__device__ __forceinline__ void issueA1(uint32_t sb, const char* abase, int arow){
    const int tid=threadIdx.x;
    const int sz=(arow>=0 && arow<HH)?16:0;
    const int rc=arow<0?0:(arow>127?127:arow);
    const char* src=abase+(size_t)rc*32768;
    const uint32_t d0=sb + 2*128;
    #pragma unroll
    for (int j=0;j<4;j++){
        const int c=tid+j*256;
        asm volatile("cp.async.cg.shared.global [%0], [%1], 16, %2;"
            :: "r"(d0+c*16), "l"(src+c*16), "r"(sz) : "memory");
        asm volatile("cp.async.cg.shared.global [%0], [%1], 16, %2;"
            :: "r"(d0+ALO+c*16), "l"(src+16384+c*16), "r"(sz) : "memory");
    }
}
__device__ __forceinline__ void issueB(uint32_t sb, const __nv_bfloat16* bptr, int buf){
    const int tid=threadIdx.x;
    const char* src=(const char*)bptr;
    const uint32_t d0=sb+BOFF+(uint32_t)buf*16384;
    #pragma unroll
    for (int j=0;j<4;j++){
        const int c=tid+j*256;
        asm volatile("cp.async.cg.shared.global [%0], [%1], 16;"
            :: "r"(d0+c*16), "l"(src+c*16) : "memory");
    }
}

__device__ __forceinline__ void do_tap2(float acc[2][4][4], uint32_t aB, uint32_t bB,
                                        int s, int m0, int n0, int l){
    #pragma unroll
    for (int ks=0;ks<4;ks++){
        const int ch = ks*2 + (l>>4);
        uint32_t ah[2][4], al[2][4], bh[2][4], bl[2][4];
        #pragma unroll
        for (int mt=0;mt<2;mt++){
            const int row = m0+mt*16+s+(l&15);
            const uint32_t ad = aB + (uint32_t)row*128 + ((uint32_t)(ch ^ ((row-2)&7))<<4);
            LDSM4(ah[mt], ad);
            LDSM4(al[mt], ad + ALO);
        }
        #pragma unroll
        for (int np=0;np<2;np++){
            const int row = n0+np*16+(l&15);
            const uint32_t bd = bB + (uint32_t)row*128 + ((uint32_t)(ch ^ (row&7))<<4);
            LDSM4(bh[np], bd);
            LDSM4(bl[np], bd + 8192);
        }
        #pragma unroll
        for (int mt=0;mt<2;mt++)
            #pragma unroll
            for (int np=0;np<2;np++)
                #pragma unroll
                for (int q=0;q<2;q++)
                    mma16816(acc[mt][np*2+q], ah[mt], bh[np][q], bh[np][2+q]);
        #pragma unroll
        for (int mt=0;mt<2;mt++)
            #pragma unroll
            for (int np=0;np<2;np++)
                #pragma unroll
                for (int q=0;q<2;q++)
                    mma16816(acc[mt][np*2+q], al[mt], bh[np][q], bh[np][2+q]);
        #pragma unroll
        for (int mt=0;mt<2;mt++)
            #pragma unroll
            for (int np=0;np<2;np++)
                #pragma unroll
                for (int q=0;q<2;q++)
                    mma16816(acc[mt][np*2+q], ah[mt], bl[np][q], bl[np][2+q]);
    }
}

__device__ void epilogue(float acc[2][4][4], const Epi& e,
                         const float* bias3, const float* bias5,
                         char* sm, int m0, int n0, int l, int h, int b){
    const int tid=threadIdx.x;
    __syncthreads();
    float* os=(float*)sm;
    #pragma unroll
    for (int mt=0;mt<2;mt++)
        #pragma unroll
        for (int nt=0;nt<4;nt++)
            #pragma unroll
            for (int q=0;q<4;q++){
                const int row=m0+mt*16+(l>>2)+((q>>1)<<3);
                const int col=n0+nt*8+((l&3)<<1)+(q&1);
                os[row*65+col]=acc[mt][nt][q];
            }
    __syncthreads();

    const int w=tid&127, oc0=(tid>>7)*32;
    const size_t pix=(size_t)h*WW+w;
    const float mv = e.map? e.map[(size_t)b*HH*WW+pix] : 0.f;
    char* smA2 = sm + BOFF;
    #pragma unroll 4
    for (int k=0;k<32;k+=2){
        float vv[2];
        #pragma unroll
        for (int s2=0;s2<2;s2++){
            const int oc=oc0+k+s2;
            const size_t idx=((size_t)(b*CC+oc))*HH*WW+pix;
            float v=os[w*65+oc];
            if (e.bias) v+=e.bias[oc];
            if (bias3)  v+=bias3[oc];
            if (bias5)  v+=bias5[oc];
            if (e.act==1)      v=fmaxf(v,0.f);
            else if (e.act==2) v=(v>0.f)?v:0.01f*v;
            if (e.res) v+=e.res[idx];
            if (e.cg)  v*=e.cg[b*CC+oc];
            if (e.map) v=v*mv+e.xres[idx];
            if (e.out) e.out[idx]=v;
            vv[s2]=v;
        }
        if (e.atout){
            const int oc=oc0+k;
            uint32_t hp, lp;
            split_pack(vv[0], vv[1], hp, lp);
            const uint32_t ro = (uint32_t)w*128 + ((uint32_t)((oc>>3)^(w&7))<<4)
                              + (uint32_t)(oc&7)*2;
            *(uint32_t*)(smA2 + ro) = hp;
            *(uint32_t*)(smA2 + 16384 + ro) = lp;
        }
    }
    if (e.atout){
        __syncthreads();
        uint4* dst=(uint4*)(e.atout + (size_t)(b*HH+h)*16384);
        const uint4* src=(const uint4*)smA2;
        #pragma unroll
        for (int j=0;j<8;j++) dst[tid+j*256]=src[tid+j*256];
    }
}

template<int KD>
__device__ void conv_one(int h, int b, const __nv_bfloat16* ain,
                         const __nv_bfloat16* wt, int bstride,
                         const Epi& e, char* sm, uint32_t sb){
    constexpr int PAD=KD/2, TAPS=KD*KD;
    const int tid=threadIdx.x, l=tid&31, wid=tid>>5;
    const int m0=(wid&3)*32, n0=(wid>>2)*32;

    __syncthreads();
    zero_pads1(sm);
    const char* abase=(const char*)ain + (size_t)b*HH*32768;

    float acc[2][4][4];
    #pragma unroll
    for (int mt=0;mt<2;mt++)
        #pragma unroll
        for (int nt=0;nt<4;nt++)
            #pragma unroll
            for (int q=0;q<4;q++) acc[mt][nt][q]=0.f;

    issueA1(sb, abase, h-PAD);
    issueB(sb, wt + (size_t)b*bstride*8192, 0);
    asm volatile("cp.async.commit_group;" ::: "memory");

    int kh=0, kw=0;
    for (int t=0;t<TAPS;t++){
        asm volatile("cp.async.wait_group 0;" ::: "memory");
        __syncthreads();
        if (t+1<TAPS){
            issueB(sb, wt + ((size_t)b*bstride + t+1)*8192, (t+1)&1);
            asm volatile("cp.async.commit_group;" ::: "memory");
        }
        do_tap2(acc, sb, sb+BOFF+(uint32_t)(t&1)*16384, 2+kw-PAD, m0, n0, l);
        kw++; if (kw==KD){kw=0; kh++;}
        if (t+1<TAPS && kw==0){
            __syncthreads();
            issueA1(sb, abase, h+kh-PAD);
            asm volatile("cp.async.commit_group;" ::: "memory");
        }
    }
    epilogue(acc, e, nullptr, nullptr, sm, m0, n0, l, h, b);
}

__device__ void mfeb_one(int h, int b,
                         const __nv_bfloat16* a1, const __nv_bfloat16* a3, const __nv_bfloat16* a5,
                         const __nv_bfloat16* w1, const __nv_bfloat16* w3, const __nv_bfloat16* w5,
                         const float* bias3, const float* bias5, const Epi& e,
                         char* sm, uint32_t sb){
    const int tid=threadIdx.x, l=tid&31, wid=tid>>5;
    const int m0=(wid&3)*32, n0=(wid>>2)*32;

    __syncthreads();
    zero_pads1(sm);
    const char* ab3=(const char*)a3 + (size_t)b*HH*32768;
    const char* ab5=(const char*)a5 + (size_t)b*HH*32768;

    float acc[2][4][4];
    #pragma unroll
    for (int mt=0;mt<2;mt++)
        #pragma unroll
        for (int nt=0;nt<4;nt++)
            #pragma unroll
            for (int q=0;q<4;q++) acc[mt][nt][q]=0.f;

    issueA1(sb, (const char*)a1 + (size_t)b*HH*32768, h);
    issueB(sb, w1, 0);
    asm volatile("cp.async.commit_group;" ::: "memory");

    for (int t=0;t<35;t++){
        asm volatile("cp.async.wait_group 0;" ::: "memory");
        __syncthreads();
        if (t<34){
            const int tn=t+1;
            const __nv_bfloat16* bp = (tn<10)? w3 + (size_t)(tn-1)*8192
                                             : w5 + (size_t)(tn-10)*8192;
            issueB(sb, bp, tn&1);
            asm volatile("cp.async.commit_group;" ::: "memory");
        }
        const int s = (t==0)? 2 : (t<10)? 1+(t-1)%3 : (t-10)%5;
        do_tap2(acc, sb, sb+BOFF+(uint32_t)(t&1)*16384, s, m0, n0, l);
        if (t<34){
            const int tn=t+1;
            bool rel; const char* asrc; int arow;
            if (tn<10){ const int u=tn-1; rel=(u%3==0); asrc=ab3; arow=h+u/3-1; }
            else      { const int u=tn-10; rel=(u%5==0); asrc=ab5; arow=h+u/5-2; }
            if (rel){
                __syncthreads();
                issueA1(sb, asrc, arow);
                asm volatile("cp.async.commit_group;" ::: "memory");
            }
        }
    }
    epilogue(acc, e, bias3, bias5, sm, m0, n0, l, h, b);
}

__device__ void stats_one(int bc, char* sm){
    const float* p = d_buf_o + (size_t)bc*HH*WW;
    const int tid=threadIdx.x;
    float* smx=(float*)sm; float* ssm=smx+256;
    __syncthreads();
    float mx=-3.4e38f, s=0.f;
    for (int i=tid;i<HH*WW;i+=256){ const float v=p[i]; mx=fmaxf(mx,v); s+=v; }
    smx[tid]=mx; ssm[tid]=s; __syncthreads();
    for (int st=128;st>0;st>>=1){
        if (tid<st){ smx[tid]=fmaxf(smx[tid],smx[tid+st]); ssm[tid]+=ssm[tid+st]; }
        __syncthreads();
    }
    if (tid==0){ d_stats[bc]=smx[0]; d_stats[BB*CC+bc]=ssm[0]*(1.f/(HH*WW)); }
}

__device__ __forceinline__ int res_tb(int c){ return (c<10)? c*36 : 360+(c-10)*36; }

// ---------------- the dataflow megakernel ----------------
__global__ __launch_bounds__(256,3) void mega(MegaArgs A, int ncta){
    extern __shared__ char smraw[];
    const uint32_t sb0=smem_u32(smraw), sb=(sb0+127)&~127u;
    char* sm = smraw + (sb-sb0);
    const int tid=threadIdx.x, cid=blockIdx.x;

    unsigned lph=0;
    if (tid==0) lph = g_phase;

    const float SCALE = 1.0f/24.0f;
    __nv_bfloat16* at_x  = d_at[0];
    __nv_bfloat16* at_bo = d_at[1];
    __nv_bfloat16* at_m1 = d_at[2];
    __nv_bfloat16* at_m3 = d_at[3];
    __nv_bfloat16* at_m5 = d_at[4];

    // zero sync state, then one barrier
    {
        uint4* fz=(uint4*)d_flag;
        for (int idx=cid*256+tid; idx<1248; idx+=ncta*256) fz[idx]=make_uint4(0,0,0,0);
        if (cid==0 && tid<46) d_segdone[tid]=0;
        if (cid==0 && tid==0) d_claim=0;
    }
    gridbar(lph, ncta);

    __shared__ unsigned s_u;
    int cg_have = -1;

    for(;;){
        __syncthreads();
        if (tid==0) s_u = atomicAdd(&d_claim, 1u);
        __syncthreads();
        const unsigned u = s_u;
        if (u >= NTOT) break;

        // ---- decode ----
        int kind, r=0, i=0, j=-1;
        if (u < 998){ kind=0; r=(int)u; }
        else if (u < 1510){ kind=1; r=(int)u-998; }
        else {
            unsigned v=u-1510;
            for(;;){ unsigned sz=(c_mfej[i]>=0)?3328u:1024u; if (v<sz) break; v-=sz; i++; }
            j = c_mfej[i];
            if (v<512){ kind=2; r=(int)v; }
            else if (v<1024){ kind=3; r=(int)v-512; }
            else if (v<1536){ kind=4; r=(int)v-1024; }
            else if (v<2048){ kind=5; r=(int)v-1536; }
            else if (v<2560){ kind=6; r=(int)v-2048; }
            else if (v<2816){ kind=7; r=(int)v-2560; }
            else { kind=8; r=(int)v-2816; }
        }
        const int h=r&127, b=r>>7;
        const int lo1 = h>0?h-1:0,  hi1 = h<127?h+1:127;
        const int lo2 = h>1?h-2:0,  hi2 = h<126?h+2:127;

        // ---- wait deps (tid0) ----
        if (tid==0){
            switch(kind){
            case 2:{ wait_cnt(39,998);
                     int inf = (i==0)?0 : (c_mfej[i-1]>=0 ? 34+c_mfej[i-1] : 2+2*(i-1));
                     wait_rows(inf,b,lo1,hi1); } break;
            case 3: wait_rows(1+2*i,b,lo1,hi1); break;
            case 4: wait_cnt(39,998); wait_rows(2+2*i,b,lo1,hi1); break;
            case 5: wait_cnt(39,998); wait_rows(2+2*i,b,lo1,hi1); break;
            case 6: wait_cnt(39,998); wait_rows(2+2*i,b,lo2,hi2); break;
            case 7: wait_cnt(2+2*i,512); break;
            case 8: wait_cnt(40+j,256);
                    wait_rows(19+3*j,b,h,h);
                    wait_rows(20+3*j,b,lo1,hi1);
                    wait_rows(21+3*j,b,lo2,hi2); break;
            default: break;
            }
            __threadfence();
        }
        __syncthreads();

        // ---- execute ----
        int flagid=-1, cntid=-1;
        switch(kind){
        case 0: prep_one(r, A, SCALE); cntid=39; break;
        case 1: ingest_one(h,b,A.x,sm); flagid=0; break;
        case 2:{
            const int c0=i*2;
            Epi e; e.bias=A.resb+(size_t)c0*CC; e.res=nullptr; e.cg=nullptr;
            e.map=nullptr; e.xres=nullptr; e.out=nullptr; e.atout=at_m1; e.act=1;
            const __nv_bfloat16* ain = (i==0)? at_x : at_bo;
            conv_one<3>(h,b, ain, d_wb+(size_t)res_tb(c0)*8192, 9, e, sm, sb);
            flagid=1+2*i; } break;
        case 3:{
            const int c1=i*2+1;
            Epi e; e.bias=A.resb+(size_t)c1*CC; e.res=(i==0)?A.x:d_buf_o; e.cg=nullptr;
            e.map=nullptr; e.xres=nullptr; e.out=d_buf_o; e.atout=at_bo; e.act=0;
            conv_one<3>(h,b, at_m1, d_wb+(size_t)res_tb(c1)*8192, 9, e, sm, sb);
            flagid=2+2*i; cntid=2+2*i; } break;
        case 4:{
            const int ca=j*2;
            Epi e; e.bias=A.mb1+(size_t)ca*CC; e.res=nullptr; e.cg=nullptr;
            e.map=nullptr; e.xres=nullptr; e.out=nullptr; e.atout=at_m1; e.act=2;
            conv_one<1>(h,b, at_bo, d_wb+(size_t)(648+ca)*8192, 0, e, sm, sb);
            flagid=19+3*j; } break;
        case 5:{
            const int ca=j*2;
            Epi e; e.bias=A.mb3+(size_t)ca*CC; e.res=nullptr; e.cg=nullptr;
            e.map=nullptr; e.xres=nullptr; e.out=nullptr; e.atout=at_m3; e.act=2;
            conv_one<3>(h,b, at_bo, d_wb+(size_t)(658+ca*9)*8192, 0, e, sm, sb);
            flagid=20+3*j; } break;
        case 6:{
            const int ca=j*2;
            Epi e; e.bias=A.mb5+(size_t)ca*CC; e.res=nullptr; e.cg=nullptr;
            e.map=nullptr; e.xres=nullptr; e.out=nullptr; e.atout=at_m5; e.act=2;
            conv_one<5>(h,b, at_bo, d_wb+(size_t)(748+ca*25)*8192, 0, e, sm, sb);
            flagid=21+3*j; } break;
        case 7: stats_one(r, sm); cntid=40+j; break;
        case 8:{
            if (cg_have != j){
                __syncthreads();
                {
                    const int bb=tid>>6, c=tid&63;
                    const float* cw1=A.caw1+(size_t)j*4*CC;
                    const float* cw2=A.caw2+(size_t)j*CC*4;
                    float se=0.f;
                    #pragma unroll
                    for (int hh=0;hh<4;hh++){
                        float hm=0.f, ha=0.f;
                        for (int ii=0;ii<CC;ii++){
                            const float wv=cw1[hh*CC+ii];
                            hm+=wv*d_stats[bb*CC+ii]; ha+=wv*d_stats[BB*CC+bb*CC+ii];
                        }
                        se+=cw2[c*4+hh]*(fmaxf(hm,0.f)+fmaxf(ha,0.f));
                    }
                    const float xll=1.f/(1.f+expf(-se));
                    ((float*)(sm+CGOFF))[tid]=
                        A.fcw[j*2+1]*(A.fcw[j*2]*xll+A.fcb[j*2])+A.fcb[j*2+1];
                }
                __syncthreads();
                cg_have = j;
            }
            const int cb=j*2+1;
            Epi e; e.bias=A.mb1+(size_t)cb*CC; e.res=nullptr;
            e.cg=(const float*)(sm+CGOFF);
            e.map=(j==4)?A.map_:nullptr; e.xres=(j==4)?A.x:nullptr;
            e.out=(j==4)?A.out:d_buf_o; e.atout=(j==4)?nullptr:at_bo; e.act=0;
            mfeb_one(h,b, at_m1, at_m3, at_m5,
                     d_wb+(size_t)(648+cb)*8192,
                     d_wb+(size_t)(658+cb*9)*8192,
                     d_wb+(size_t)(748+cb*25)*8192,
                     A.mb3+(size_t)cb*CC, A.mb5+(size_t)cb*CC, e, sm, sb);
            flagid=34+j; } break;
        }

        // ---- publish completion ----
        __syncthreads();
        if (tid==0){
            __threadfence();
            if (flagid>=0) ((volatile unsigned char*)d_flag)[flagid*512 + r] = 1;
            if (cntid>=0)  atomicAdd(&d_segdone[cntid], 1u);
        }
    }
}

extern "C" void kernel_launch(void* const* d_in, const int* in_sizes, int n_in,
                              void* d_out, int out_size)
{
    MegaArgs A;
    A.x    = (const float*)d_in[0];
    A.cf1  = (const float*)d_in[1];
    A.cf2  = (const float*)d_in[2];
    A.map_ = (const float*)d_in[3];
    A.resw = (const float*)d_in[4];
    A.resb = (const float*)d_in[5];
    A.mw1  = (const float*)d_in[6];
    A.mb1  = (const float*)d_in[7];
    A.mw3  = (const float*)d_in[8];
    A.mb3  = (const float*)d_in[9];
    A.mw5  = (const float*)d_in[10];
    A.mb5  = (const float*)d_in[11];
    A.caw1 = (const float*)d_in[12];
    A.caw2 = (const float*)d_in[13];
    A.fcw  = (const float*)d_in[14];
    A.fcb  = (const float*)d_in[15];
    A.out  = (float*)d_out;

    cudaFuncSetAttribute(mega, cudaFuncAttributeMaxDynamicSharedMemorySize, SMEMSZ);

    int dev=0, sms=0, occ=0;
    cudaGetDevice(&dev);
    cudaDeviceGetAttribute(&sms, cudaDevAttrMultiProcessorCount, dev);
    cudaOccupancyMaxActiveBlocksPerMultiprocessor(&occ, mega, 256, SMEMSZ);
    if (occ < 1) occ = 1;
    int ncta = sms * occ;
    if (ncta < 1) ncta = 1;
    if (ncta > 512) ncta = 512;

    mega<<<ncta, 256, SMEMSZ>>>(A, ncta);
}